// round 2
// baseline (speedup 1.0000x reference)
#include <cuda_runtime.h>
#include <cuda_bf16.h>
#include <cstdint>

// Problem constants
#define B   16
#define T   512
#define H   2048
#define TH  (T * H)          // 1048576 floats per batch in out
#define WLD (2 * H)          // 4096, row stride of W

// ---------------- barrier state (device global, no allocation) -------------
#define NBLK 128
__device__ unsigned g_bar[T];   // one counter per step

__global__ void zero_bar_kernel() {
    int i = threadIdx.x;
    if (i < T) g_bar[i] = 0u;
}

// ===========================================================================
// Phase 1: u[m, g] = sum_k x[m, k] * W[g, k] + b[g]      (NT GEMM)
// m = b*T + t over 8192 rows; g over 2048; k over 2048 (W cols [0, H)).
// 128x128x8 register-blocked SGEMM, 256 threads, 8x8 microtile.
// ===========================================================================
#define BM 128
#define BN 128
#define BK 8
#define TM 8
#define TN 8
#define LDP (BM + 4)   // padded smem row

__global__ __launch_bounds__(256, 2)
void gemm_u_kernel(const float* __restrict__ x,
                   const float* __restrict__ W,
                   const float* __restrict__ bias,
                   float* __restrict__ out)
{
    __shared__ float As[BK][LDP];
    __shared__ float Bs[BK][LDP];

    const int bx = blockIdx.x;   // n tile: 0..15  (g)
    const int by = blockIdx.y;   // m tile: 0..63
    const int tid = threadIdx.x;
    const int tx = tid % 16;
    const int ty = tid / 16;

    // A loading: thread reads one float4 along K from x.
    const int aRow = tid >> 1;          // 0..127 (m within tile)
    const int aCol = (tid & 1) * 4;     // 0 or 4 (k within tile)
    // B loading: thread reads one float4 along K from W row (NT!).
    const int bRow = tid >> 1;          // 0..127 (n within tile = W row)
    const int bCol = (tid & 1) * 4;     // 0 or 4 (k within tile)

    const float* Aptr = x + (size_t)(by * BM) * H;
    const float* Bptr = W + (size_t)(bx * BN) * WLD;   // W rows n0.., cols [0,H)

    float acc[TM][TN];
#pragma unroll
    for (int i = 0; i < TM; i++)
#pragma unroll
        for (int j = 0; j < TN; j++) acc[i][j] = 0.0f;

    for (int k0 = 0; k0 < H; k0 += BK) {
        float4 a4 = *(const float4*)(Aptr + (size_t)aRow * H + k0 + aCol);
        As[aCol + 0][aRow] = a4.x;
        As[aCol + 1][aRow] = a4.y;
        As[aCol + 2][aRow] = a4.z;
        As[aCol + 3][aRow] = a4.w;
        // NT: Bs[kk][n] = W[(n0+n)*WLD + k0+kk]
        float4 b4 = *(const float4*)(Bptr + (size_t)bRow * WLD + k0 + bCol);
        Bs[bCol + 0][bRow] = b4.x;
        Bs[bCol + 1][bRow] = b4.y;
        Bs[bCol + 2][bRow] = b4.z;
        Bs[bCol + 3][bRow] = b4.w;
        __syncthreads();

#pragma unroll
        for (int kk = 0; kk < BK; kk++) {
            float a[TM], b[TN];
            float4 av0 = *(const float4*)&As[kk][ty * TM];
            float4 av1 = *(const float4*)&As[kk][ty * TM + 4];
            a[0]=av0.x; a[1]=av0.y; a[2]=av0.z; a[3]=av0.w;
            a[4]=av1.x; a[5]=av1.y; a[6]=av1.z; a[7]=av1.w;
            float4 bv0 = *(const float4*)&Bs[kk][tx * TN];
            float4 bv1 = *(const float4*)&Bs[kk][tx * TN + 4];
            b[0]=bv0.x; b[1]=bv0.y; b[2]=bv0.z; b[3]=bv0.w;
            b[4]=bv1.x; b[5]=bv1.y; b[6]=bv1.z; b[7]=bv1.w;
#pragma unroll
            for (int i = 0; i < TM; i++)
#pragma unroll
                for (int j = 0; j < TN; j++)
                    acc[i][j] = fmaf(a[i], b[j], acc[i][j]);
        }
        __syncthreads();
    }

    const int m0 = by * BM + ty * TM;
    const int n0 = bx * BN + tx * TN;
    float4 bias0 = *(const float4*)(bias + n0);
    float4 bias1 = *(const float4*)(bias + n0 + 4);
#pragma unroll
    for (int i = 0; i < TM; i++) {
        float4 c0, c1;
        c0.x = acc[i][0] + bias0.x; c0.y = acc[i][1] + bias0.y;
        c0.z = acc[i][2] + bias0.z; c0.w = acc[i][3] + bias0.w;
        c1.x = acc[i][4] + bias1.x; c1.y = acc[i][5] + bias1.y;
        c1.z = acc[i][6] + bias1.z; c1.w = acc[i][7] + bias1.w;
        *(float4*)(out + (size_t)(m0 + i) * H + n0)     = c0;
        *(float4*)(out + (size_t)(m0 + i) * H + n0 + 4) = c1;
    }
}

// ===========================================================================
// Phase 2: persistent sequential recurrence
//   h_t[b,g] = u_t[b,g] + sum_k h_{t-1}[b,k] * W[g, H+k]
// out[:, t, :] holds u_t; blocks atomically add their k-partials into it.
//
// Grid: 128 blocks = 16 g-tiles (Gtile=128) x 8 k-tiles (Ktile=256).
// Block W slice (128 g rows x 256 k cols x 4B = 128 KB) staged in SMEM once.
// 256 threads = 64 g-pairs x 4 k-subsplits; thread tile = 16b x 2g x 64k.
// Intra-block ksub reduction via padded SMEM scratch, then 8 REDs/thread.
// ===========================================================================
#define GTILE  128
#define KTILE  256
#define NKSUB  4
#define KSUBR  (KTILE / NKSUB)     // 64
#define REDROW 132                 // 4*32 + 4 pad (floats)

// smem layout (floats):
//   ws  [KTILE][GTILE]      : 256*128   = 32768  (W slice, ws[k][g])
//   hs  [B][KTILE]          : 16*256    = 4096
//   red [64][REDROW]        : 64*132    = 8448
#define WS_OFF  0
#define HS_OFF  (KTILE * GTILE)                 // 32768
#define RED_OFF (HS_OFF + B * KTILE)            // 36864
#define SMEM_FLOATS (RED_OFF + 64 * REDROW)     // 45312
#define SMEM_BYTES  (SMEM_FLOATS * 4)           // 181248

__device__ __forceinline__ float ld_cg(const float* p) {
    float v;
    asm volatile("ld.global.cg.f32 %0, [%1];" : "=f"(v) : "l"(p));
    return v;
}
__device__ __forceinline__ float4 ld_cg4(const float* p) {
    float4 v;
    asm volatile("ld.global.cg.v4.f32 {%0,%1,%2,%3}, [%4];"
                 : "=f"(v.x), "=f"(v.y), "=f"(v.z), "=f"(v.w) : "l"(p));
    return v;
}

__global__ __launch_bounds__(256, 1)
void rnn_scan_kernel(const float* __restrict__ W,
                     float* __restrict__ out)
{
    extern __shared__ float smem[];
    float* ws  = smem + WS_OFF;
    float* hs  = smem + HS_OFF;
    float* red = smem + RED_OFF;

    const int bid = blockIdx.x;
    const int gi  = bid & 15;          // 16 g-tiles
    const int ki  = bid >> 4;          // 8 k-tiles
    const int g0  = gi * GTILE;
    const int k0  = ki * KTILE;

    const int tid = threadIdx.x;
    const int glp = tid & 63;          // g-pair index: g_local = glp*2 + j
    const int ks  = tid >> 6;          // k-subsplit 0..3
    const int kbeg = ks * KSUBR;

    // ---- stage W slice into smem: ws[k][g] = W[(g0+g)*WLD + H + k0 + k] ----
    // coalesced gmem reads (float4 along k), scattered STS (once).
#pragma unroll
    for (int it = 0; it < 32; it++) {
        int fi = tid + it * 256;               // 0..8191
        int g  = fi >> 6;                      // 0..127
        int c  = fi & 63;                      // float4 chunk along k
        float4 w4 = *(const float4*)(W + (size_t)(g0 + g) * WLD + H + k0 + c * 4);
        ws[(c * 4 + 0) * GTILE + g] = w4.x;
        ws[(c * 4 + 1) * GTILE + g] = w4.y;
        ws[(c * 4 + 2) * GTILE + g] = w4.z;
        ws[(c * 4 + 3) * GTILE + g] = w4.w;
    }
    __syncthreads();

    for (int t = 1; t < T; t++) {
        // ---- load h_{t-1} slice (16 x 256) into hs, coalesced ----
#pragma unroll
        for (int r = 0; r < 4; r++) {
            int fi = tid + r * 256;            // float4 index 0..1023
            int b  = fi >> 6;                  // 0..15
            int c  = fi & 63;
            float4 h4 = ld_cg4(out + (size_t)b * TH + (size_t)(t - 1) * H + k0 + c * 4);
            *(float4*)&hs[b * KTILE + c * 4] = h4;
        }
        __syncthreads();

        // ---- compute: acc[b][j] = sum_{k in my ksub} hs[b][k] * ws[k][glp*2+j]
        float acc[B][2];
#pragma unroll
        for (int i = 0; i < B; i++) { acc[i][0] = 0.0f; acc[i][1] = 0.0f; }

        const float* wsp = ws + kbeg * GTILE + glp * 2;
        const float* hsp = hs + kbeg;
#pragma unroll 2
        for (int kc = 0; kc < KSUBR; kc += 4) {
            float2 w0 = *(const float2*)(wsp + (kc + 0) * GTILE);
            float2 w1 = *(const float2*)(wsp + (kc + 1) * GTILE);
            float2 w2 = *(const float2*)(wsp + (kc + 2) * GTILE);
            float2 w3 = *(const float2*)(wsp + (kc + 3) * GTILE);
#pragma unroll
            for (int b = 0; b < B; b++) {
                float4 h4 = *(const float4*)(hsp + b * KTILE + kc);
                acc[b][0] = fmaf(h4.x, w0.x, acc[b][0]);
                acc[b][1] = fmaf(h4.x, w0.y, acc[b][1]);
                acc[b][0] = fmaf(h4.y, w1.x, acc[b][0]);
                acc[b][1] = fmaf(h4.y, w1.y, acc[b][1]);
                acc[b][0] = fmaf(h4.z, w2.x, acc[b][0]);
                acc[b][1] = fmaf(h4.z, w2.y, acc[b][1]);
                acc[b][0] = fmaf(h4.w, w3.x, acc[b][0]);
                acc[b][1] = fmaf(h4.w, w3.y, acc[b][1]);
            }
        }
        __syncthreads();   // previous step's red reads are done (barrier), and
                           // everyone finished reading hs before reuse below

        // ---- store partials: red[glp][ks*32 + s], s = j*16 + b ----
        {
            float* rp = red + glp * REDROW + ks * 32;
#pragma unroll
            for (int j = 0; j < 2; j++)
#pragma unroll
                for (int bq = 0; bq < 4; bq++) {
                    float4 v;
                    v.x = acc[bq * 4 + 0][j];
                    v.y = acc[bq * 4 + 1][j];
                    v.z = acc[bq * 4 + 2][j];
                    v.w = acc[bq * 4 + 3][j];
                    *(float4*)(rp + j * 16 + bq * 4) = v;
                }
        }
        __syncthreads();

        // ---- reduce over ks and atomically add into out[:, t, :] ----
        {
            const int rglp = tid & 63;
            const int half = tid >> 6;        // 0..3 -> slots half*8..half*8+7
            const float* rp = red + rglp * REDROW + half * 8;
            float4 s0 = *(const float4*)(rp + 0 * 32);
            float4 s1 = *(const float4*)(rp + 0 * 32 + 4);
            float4 a0 = *(const float4*)(rp + 1 * 32);
            float4 a1 = *(const float4*)(rp + 1 * 32 + 4);
            s0.x += a0.x; s0.y += a0.y; s0.z += a0.z; s0.w += a0.w;
            s1.x += a1.x; s1.y += a1.y; s1.z += a1.z; s1.w += a1.w;
            a0 = *(const float4*)(rp + 2 * 32);
            a1 = *(const float4*)(rp + 2 * 32 + 4);
            s0.x += a0.x; s0.y += a0.y; s0.z += a0.z; s0.w += a0.w;
            s1.x += a1.x; s1.y += a1.y; s1.z += a1.z; s1.w += a1.w;
            a0 = *(const float4*)(rp + 3 * 32);
            a1 = *(const float4*)(rp + 3 * 32 + 4);
            s0.x += a0.x; s0.y += a0.y; s0.z += a0.z; s0.w += a0.w;
            s1.x += a1.x; s1.y += a1.y; s1.z += a1.z; s1.w += a1.w;

            float v[8] = {s0.x, s0.y, s0.z, s0.w, s1.x, s1.y, s1.z, s1.w};
#pragma unroll
            for (int i = 0; i < 8; i++) {
                int s  = half * 8 + i;
                int jj = s >> 4;              // 0/1
                int b  = s & 15;
                float* op = out + (size_t)b * TH + (size_t)t * H + g0 + rglp * 2 + jj;
                atomicAdd(op, v[i]);
            }
        }

        // ---- global step barrier ----
        __threadfence();
        __syncthreads();
        if (t < T - 1) {
            if (tid == 0) {
                atomicAdd(&g_bar[t], 1u);
                volatile unsigned* p = &g_bar[t];
                while (*p < NBLK) { __nanosleep(32); }
                __threadfence();
            }
            __syncthreads();
        }
    }
}

// ---------------- h_last copy ----------------------------------------------
__global__ void hlast_kernel(const float* __restrict__ out,
                             float* __restrict__ hlast)
{
    int i = blockIdx.x * blockDim.x + threadIdx.x;
    if (i < B * H) {
        int b = i / H;
        int g = i % H;
        hlast[i] = out[(size_t)b * TH + (size_t)(T - 1) * H + g];
    }
}

// ---------------- launch ----------------------------------------------------
extern "C" void kernel_launch(void* const* d_in, const int* in_sizes, int n_in,
                              void* d_out, int out_size)
{
    const float* x  = (const float*)d_in[0];   // (B, T, H)
    const float* W  = (const float*)d_in[1];   // (H, 2H)
    const float* bi = (const float*)d_in[2];   // (H,)
    float* out = (float*)d_out;                // (B,T,H) then (B,H)

    // opt-in to large dynamic smem (idempotent; not an allocation)
    static int smem_set = 0;
    if (!smem_set) {
        cudaFuncSetAttribute(rnn_scan_kernel,
                             cudaFuncAttributeMaxDynamicSharedMemorySize,
                             SMEM_BYTES);
        smem_set = 1;
    }

    // reset step barriers
    zero_bar_kernel<<<1, T>>>();

    // Phase 1: u -> out[:, :, :]
    dim3 ggrid(H / BN, (B * T) / BM);          // (16, 64)
    gemm_u_kernel<<<ggrid, 256>>>(x, W, bi, out);

    // Phase 2: persistent scan (128 blocks, all co-resident)
    rnn_scan_kernel<<<NBLK, 256, SMEM_BYTES>>>(W, out);

    // h_last
    if (out_size >= B * T * H + B * H) {
        hlast_kernel<<<(B * H + 255) / 256, 256>>>(out, out + (size_t)B * T * H);
    }
}

// round 3
// speedup vs baseline: 1.6616x; 1.6616x over previous
#include <cuda_runtime.h>
#include <cuda_bf16.h>
#include <cstdint>

#define B_  16
#define T_  512
#define H_  2048
#define TH_ (T_ * H_)        // 1048576
#define WLD 4096             // W row stride (floats)

// ---------------- barrier + split buffers (device globals) ------------------
#define NBLK 128
__device__ unsigned g_bar[T_];

__device__ __nv_bfloat16 g_xh[(size_t)B_ * T_ * H_];
__device__ __nv_bfloat16 g_xl[(size_t)B_ * T_ * H_];
__device__ __nv_bfloat16 g_wxh[(size_t)H_ * H_];
__device__ __nv_bfloat16 g_wxl[(size_t)H_ * H_];
__device__ __nv_bfloat16 g_whh[(size_t)H_ * H_];
__device__ __nv_bfloat16 g_whl[(size_t)H_ * H_];

__global__ void zero_bar_kernel() { g_bar[threadIdx.x] = 0u; }

// ---------------- helpers ---------------------------------------------------
__device__ __forceinline__ uint32_t smem_u32(const void* p) {
    return (uint32_t)__cvta_generic_to_shared(p);
}
__device__ __forceinline__ void cp16(uint32_t s, const void* g) {
    asm volatile("cp.async.cg.shared.global [%0], [%1], 16;" :: "r"(s), "l"(g));
}
#define CP_COMMIT() asm volatile("cp.async.commit_group;")
#define CP_WAIT1()  asm volatile("cp.async.wait_group 1;")

__device__ __forceinline__ void ldsm4(uint32_t (&r)[4], uint32_t addr) {
    asm volatile("ldmatrix.sync.aligned.m8n8.x4.shared.b16 {%0,%1,%2,%3}, [%4];"
                 : "=r"(r[0]), "=r"(r[1]), "=r"(r[2]), "=r"(r[3]) : "r"(addr));
}
__device__ __forceinline__ void mma16816(float (&c)[4], const uint32_t (&a)[4],
                                         uint32_t b0, uint32_t b1) {
    asm volatile("mma.sync.aligned.m16n8k16.row.col.f32.bf16.bf16.f32 "
                 "{%0,%1,%2,%3}, {%4,%5,%6,%7}, {%8,%9}, {%0,%1,%2,%3};"
                 : "+f"(c[0]), "+f"(c[1]), "+f"(c[2]), "+f"(c[3])
                 : "r"(a[0]), "r"(a[1]), "r"(a[2]), "r"(a[3]), "r"(b0), "r"(b1));
}
__device__ __forceinline__ float4 ld_cg4(const float* p) {
    float4 v;
    asm volatile("ld.global.cg.v4.f32 {%0,%1,%2,%3}, [%4];"
                 : "=f"(v.x), "=f"(v.y), "=f"(v.z), "=f"(v.w) : "l"(p));
    return v;
}

// ---------------- prepass: hi/lo bf16 splits --------------------------------
__global__ void split_x_kernel(const float* __restrict__ x) {
    size_t fi = (size_t)blockIdx.x * blockDim.x + threadIdx.x;   // float4 idx
    if (fi >= (size_t)B_ * T_ * H_ / 4) return;
    float4 v = *(const float4*)(x + fi * 4);
    union { __nv_bfloat16 b[4]; uint2 u; } hh, ll;
    float f[4] = {v.x, v.y, v.z, v.w};
#pragma unroll
    for (int i = 0; i < 4; i++) {
        hh.b[i] = __float2bfloat16_rn(f[i]);
        ll.b[i] = __float2bfloat16_rn(f[i] - __bfloat162float(hh.b[i]));
    }
    *(uint2*)(g_xh + fi * 4) = hh.u;
    *(uint2*)(g_xl + fi * 4) = ll.u;
}

__global__ void split_w_kernel(const float* __restrict__ W) {
    size_t fi = (size_t)blockIdx.x * blockDim.x + threadIdx.x;   // float4 idx
    if (fi >= (size_t)H_ * H_ / 4) return;
    int g = (int)(fi >> 9);
    int c = (int)(fi & 511) * 4;
    const float* base = W + (size_t)g * WLD;

    float4 v = *(const float4*)(base + c);                 // Wx part
    union { __nv_bfloat16 b[4]; uint2 u; } hh, ll;
    float f[4] = {v.x, v.y, v.z, v.w};
#pragma unroll
    for (int i = 0; i < 4; i++) {
        hh.b[i] = __float2bfloat16_rn(f[i]);
        ll.b[i] = __float2bfloat16_rn(f[i] - __bfloat162float(hh.b[i]));
    }
    *(uint2*)(g_wxh + (size_t)g * H_ + c) = hh.u;
    *(uint2*)(g_wxl + (size_t)g * H_ + c) = ll.u;

    v = *(const float4*)(base + H_ + c);                   // Wh part
    float f2[4] = {v.x, v.y, v.z, v.w};
#pragma unroll
    for (int i = 0; i < 4; i++) {
        hh.b[i] = __float2bfloat16_rn(f2[i]);
        ll.b[i] = __float2bfloat16_rn(f2[i] - __bfloat162float(hh.b[i]));
    }
    *(uint2*)(g_whh + (size_t)g * H_ + c) = hh.u;
    *(uint2*)(g_whl + (size_t)g * H_ + c) = ll.u;
}

// ===========================================================================
// Phase 1: u[m,g] = sum_k x[m,k] W[g,k] + b[g]  via 3x bf16 split mma.
// 128x128x32 tiles, 256 thr = 8 warps (4m x 2n), warp tile 32m x 64n.
// ===========================================================================
#define P1_ST 40            // padded smem row stride (bf16 elems)
#define P1_TILE (128 * P1_ST)
#define P1_SMEM_BYTES (4 * P1_TILE * 2)   // 40960

__global__ __launch_bounds__(256, 2)
void gemm_u_mma(const float* __restrict__ bias, float* __restrict__ out)
{
    extern __shared__ __align__(16) __nv_bfloat16 sm[];
    __nv_bfloat16* As[2] = { sm,               sm + P1_TILE };
    __nv_bfloat16* Bs[2] = { sm + 2 * P1_TILE, sm + 3 * P1_TILE };

    const int tid = threadIdx.x, lane = tid & 31, wid = tid >> 5;
    const int m0 = blockIdx.y * 128, g0 = blockIdx.x * 128;
    const int wm = wid & 3, wn = wid >> 2;

    const __nv_bfloat16* Ag[3] = { g_xh, g_xh, g_xl };
    const __nv_bfloat16* Bg[3] = { g_wxh, g_wxl, g_wxh };

    const int lrow = tid >> 1;
    const int lco  = (tid & 1) * 16;     // 0 or 16 (bf16 elems)

    float acc[2][8][4];
#pragma unroll
    for (int i = 0; i < 2; i++)
#pragma unroll
        for (int j = 0; j < 8; j++)
#pragma unroll
            for (int q = 0; q < 4; q++) acc[i][j][q] = 0.0f;

#define P1_ISSUE(st, it) do {                                                  \
        int _p = (it) >> 6, _kk = ((it) & 63) * 32;                            \
        const __nv_bfloat16* _ga = Ag[_p] + (size_t)(m0 + lrow) * H_ + _kk + lco; \
        const __nv_bfloat16* _gb = Bg[_p] + (size_t)(g0 + lrow) * H_ + _kk + lco; \
        uint32_t _sa = smem_u32(As[st] + lrow * P1_ST + lco);                  \
        uint32_t _sb = smem_u32(Bs[st] + lrow * P1_ST + lco);                  \
        cp16(_sa, _ga); cp16(_sa + 16, _ga + 8);                               \
        cp16(_sb, _gb); cp16(_sb + 16, _gb + 8);                               \
    } while (0)

    P1_ISSUE(0, 0);
    CP_COMMIT();

    const int NT = 192;      // 3 passes x 64 k-iters
    for (int it = 0; it < NT; ++it) {
        if (it + 1 < NT) P1_ISSUE((it + 1) & 1, it + 1);
        CP_COMMIT();
        CP_WAIT1();
        __syncthreads();

        const __nv_bfloat16* A_s = As[it & 1];
        const __nv_bfloat16* B_s = Bs[it & 1];
#pragma unroll
        for (int kq = 0; kq < 2; kq++) {
            uint32_t a[2][4];
#pragma unroll
            for (int mt = 0; mt < 2; mt++)
                ldsm4(a[mt], smem_u32(A_s + (wm * 32 + mt * 16 + (lane & 15)) * P1_ST
                                          + kq * 16 + ((lane >> 4) << 3)));
            uint32_t bf[4][4];
#pragma unroll
            for (int ng = 0; ng < 4; ng++)
                ldsm4(bf[ng], smem_u32(B_s + (wn * 64 + ng * 16 + (lane & 7) + ((lane & 16) >> 1)) * P1_ST
                                           + kq * 16 + (lane & 8)));
#pragma unroll
            for (int mt = 0; mt < 2; mt++)
#pragma unroll
                for (int ng = 0; ng < 4; ng++) {
                    mma16816(acc[mt][2 * ng],     a[mt], bf[ng][0], bf[ng][1]);
                    mma16816(acc[mt][2 * ng + 1], a[mt], bf[ng][2], bf[ng][3]);
                }
        }
        __syncthreads();
    }

    // epilogue: + bias, fp32 store
    const int r0 = lane >> 2, c0 = (lane & 3) * 2;
#pragma unroll
    for (int mt = 0; mt < 2; mt++) {
        int m = m0 + wm * 32 + mt * 16 + r0;
#pragma unroll
        for (int nt = 0; nt < 8; nt++) {
            int g = g0 + wn * 64 + nt * 8 + c0;
            float bx = bias[g], by = bias[g + 1];
            float2 v0 = { acc[mt][nt][0] + bx, acc[mt][nt][1] + by };
            float2 v1 = { acc[mt][nt][2] + bx, acc[mt][nt][3] + by };
            *(float2*)(out + (size_t)m * H_ + g)       = v0;
            *(float2*)(out + (size_t)(m + 8) * H_ + g) = v1;
        }
    }
}

// ===========================================================================
// Phase 2: persistent scan with mma. h_t = u_t + h_{t-1} @ Wh^T.
// 128 blocks = 16 g-tiles(128) x 8 k-tiles(256). Wh hi/lo tiles in smem.
// 8 warps, warp owns 16 g-cols; m16 = the 16 batches. 96 HMMA/warp/step.
// ===========================================================================
#define SC_ST 264                     // padded row stride (bf16 elems)
#define SC_WHH 0
#define SC_WHL (128 * SC_ST)          // 33792
#define SC_HH  (2 * 128 * SC_ST)      // 67584
#define SC_HL  (SC_HH + 16 * SC_ST)   // 71808
#define SC_SMEM_ELEMS (SC_HL + 16 * SC_ST)
#define SC_SMEM_BYTES (SC_SMEM_ELEMS * 2)   // 152064

__global__ __launch_bounds__(256, 1)
void rnn_scan_mma(float* __restrict__ out)
{
    extern __shared__ __align__(16) __nv_bfloat16 sm[];
    __nv_bfloat16* whh_s = sm + SC_WHH;
    __nv_bfloat16* whl_s = sm + SC_WHL;
    __nv_bfloat16* hh_s  = sm + SC_HH;
    __nv_bfloat16* hl_s  = sm + SC_HL;

    const int tid = threadIdx.x, lane = tid & 31, wid = tid >> 5;
    const int gi = blockIdx.x & 15, ki = blockIdx.x >> 4;
    const int g0 = gi * 128, k0 = ki * 256;

    // stage Wh hi/lo tile: rows g (128), cols k (256)
    for (int c = tid; c < 128 * 32; c += 256) {
        int row = c >> 5, cc = (c & 31) * 8;
        *(uint4*)(whh_s + row * SC_ST + cc) =
            *(const uint4*)(g_whh + (size_t)(g0 + row) * H_ + k0 + cc);
        *(uint4*)(whl_s + row * SC_ST + cc) =
            *(const uint4*)(g_whl + (size_t)(g0 + row) * H_ + k0 + cc);
    }
    __syncthreads();

    const int n0w = wid * 16;
    const int r0 = lane >> 2, c0 = (lane & 3) * 2;

    for (int t = 1; t < T_; ++t) {
        // ---- load h_{t-1} slice (16 x 256 fp32), split to bf16 hi/lo ----
#pragma unroll
        for (int i = 0; i < 4; i++) {
            int fi = tid + i * 256;            // float4 index 0..1023
            int b = fi >> 6, c = (fi & 63) * 4;
            float4 h4 = ld_cg4(out + (size_t)b * TH_ + (size_t)(t - 1) * H_ + k0 + c);
            union { __nv_bfloat16 bb[4]; uint2 u; } th, tl;
            float f[4] = {h4.x, h4.y, h4.z, h4.w};
#pragma unroll
            for (int q = 0; q < 4; q++) {
                th.bb[q] = __float2bfloat16_rn(f[q]);
                tl.bb[q] = __float2bfloat16_rn(f[q] - __bfloat162float(th.bb[q]));
            }
            *(uint2*)(hh_s + b * SC_ST + c) = th.u;
            *(uint2*)(hl_s + b * SC_ST + c) = tl.u;
        }
        __syncthreads();

        // ---- 3-pass split mma: hh*Whh + hh*Whl + hl*Whh ----
        float acc[2][4];
#pragma unroll
        for (int i = 0; i < 2; i++)
#pragma unroll
            for (int q = 0; q < 4; q++) acc[i][q] = 0.0f;

#pragma unroll
        for (int pass = 0; pass < 3; pass++) {
            const __nv_bfloat16* A_s = (pass < 2) ? hh_s : hl_s;
            const __nv_bfloat16* B_s = (pass == 1) ? whl_s : whh_s;
            const uint32_t abase = smem_u32(A_s + (lane & 15) * SC_ST + ((lane >> 4) << 3));
            const uint32_t bbase = smem_u32(B_s + (n0w + (lane & 7) + ((lane & 16) >> 1)) * SC_ST
                                                + (lane & 8));
#pragma unroll
            for (int kq = 0; kq < 16; kq++) {
                uint32_t a[4], bf[4];
                ldsm4(a,  abase + kq * 32);    // 16 bf16 = 32 bytes
                ldsm4(bf, bbase + kq * 32);
                mma16816(acc[0], a, bf[0], bf[1]);
                mma16816(acc[1], a, bf[2], bf[3]);
            }
        }

        // ---- add partials into out[:, t, :] (holds u_t) ----
        float* obase = out + (size_t)t * H_ + g0 + n0w + c0;
#pragma unroll
        for (int nt = 0; nt < 2; nt++) {
            float* p0 = obase + nt * 8 + (size_t)r0 * TH_;
            atomicAdd(p0,     acc[nt][0]);
            atomicAdd(p0 + 1, acc[nt][1]);
            float* p1 = obase + nt * 8 + (size_t)(r0 + 8) * TH_;
            atomicAdd(p1,     acc[nt][2]);
            atomicAdd(p1 + 1, acc[nt][3]);
        }

        // ---- global step barrier ----
        __threadfence();
        __syncthreads();
        if (t < T_ - 1) {
            if (tid == 0) {
                atomicAdd(&g_bar[t], 1u);
                volatile unsigned* p = &g_bar[t];
                while (*p < NBLK) { __nanosleep(32); }
                __threadfence();
            }
            __syncthreads();
        }
    }
}

// ---------------- h_last copy ----------------------------------------------
__global__ void hlast_kernel(const float* __restrict__ out,
                             float* __restrict__ hlast)
{
    int i = blockIdx.x * blockDim.x + threadIdx.x;
    if (i < B_ * H_) {
        int b = i / H_;
        int g = i % H_;
        hlast[i] = out[(size_t)b * TH_ + (size_t)(T_ - 1) * H_ + g];
    }
}

// ---------------- launch ----------------------------------------------------
extern "C" void kernel_launch(void* const* d_in, const int* in_sizes, int n_in,
                              void* d_out, int out_size)
{
    const float* x  = (const float*)d_in[0];   // (B, T, H)
    const float* W  = (const float*)d_in[1];   // (H, 2H)
    const float* bi = (const float*)d_in[2];   // (H,)
    float* out = (float*)d_out;                // (B,T,H) then (B,H)

    cudaFuncSetAttribute(gemm_u_mma,
                         cudaFuncAttributeMaxDynamicSharedMemorySize,
                         P1_SMEM_BYTES);
    cudaFuncSetAttribute(rnn_scan_mma,
                         cudaFuncAttributeMaxDynamicSharedMemorySize,
                         SC_SMEM_BYTES);

    // barriers + splits
    zero_bar_kernel<<<1, T_>>>();
    split_x_kernel<<<(B_ * T_ * H_ / 4 + 255) / 256, 256>>>(x);
    split_w_kernel<<<(H_ * H_ / 4 + 255) / 256, 256>>>(W);

    // Phase 1: u -> out
    dim3 ggrid(H_ / 128, (B_ * T_) / 128);     // (16, 64)
    gemm_u_mma<<<ggrid, 256, P1_SMEM_BYTES>>>(bi, out);

    // Phase 2: persistent scan
    rnn_scan_mma<<<NBLK, 256, SC_SMEM_BYTES>>>(out);

    // h_last
    if (out_size >= B_ * T_ * H_ + B_ * H_) {
        hlast_kernel<<<(B_ * H_ + 255) / 256, 256>>>(out, out + (size_t)B_ * T_ * H_);
    }
}